// round 1
// baseline (speedup 1.0000x reference)
#include <cuda_runtime.h>
#include <math.h>

// ---------------------------------------------------------------------------
// Problem constants (fixed by the dataset)
// ---------------------------------------------------------------------------
#define G_NUM  1024
#define P_N    75
#define DEG_E  8
#define N_N    (G_NUM * P_N)      // 76800 nodes
#define E_N    (N_N * DEG_E)      // 614400 edges
#define EPG    (P_N * DEG_E)      // 600 edges / graph
#define RPG    (EPG * 4)          // 2400 (edge,corner) records / graph
#define KS_C   5
#define KK_C   25
#define NT     256                // threads per CTA everywhere

struct Rec { unsigned sd; float w; };   // sd = src | (dst<<8) (graph-local), w = basis weight

// ---------------------------------------------------------------------------
// Scratch (device globals -- no allocation allowed)
// ---------------------------------------------------------------------------
__device__ Rec   d_records[G_NUM * RPG];        // ~19.7 MB, sorted by k per graph
__device__ int   d_off[G_NUM * (KK_C + 1)];     // CSR offsets per graph
__device__ float d_h1[N_N * 32];
__device__ float d_h2[N_N * 64];
__device__ float d_h3[N_N * 64];

__device__ __forceinline__ float elu_f(float v) { return v > 0.0f ? v : expm1f(v); }

// ---------------------------------------------------------------------------
// Kernel 0: spline basis + counting sort of (edge,corner) records by k
// ---------------------------------------------------------------------------
__global__ __launch_bounds__(NT)
void bucket_kernel(const int* __restrict__ edge_index, const float* __restrict__ edge_attr) {
    __shared__ Rec  rec[RPG];
    __shared__ unsigned char kk[RPG];
    __shared__ int  cnt[KK_C], cur[KK_C], off[KK_C + 1];

    const int g = blockIdx.x, tid = threadIdx.x;
    if (tid < KK_C) { cnt[tid] = 0; cur[tid] = 0; }
    __syncthreads();

    for (int el = tid; el < EPG; el += NT) {
        const int e  = g * EPG + el;
        const float u0 = edge_attr[2 * e], u1 = edge_attr[2 * e + 1];
        const int src = edge_index[e]         - g * P_N;
        const int dst = edge_index[E_N + e]   - g * P_N;

        float p0 = u0 * (KS_C - 1), p1 = u1 * (KS_C - 1);
        float l0 = fminf(fmaxf(floorf(p0), 0.0f), (float)(KS_C - 1));
        float l1 = fminf(fmaxf(floorf(p1), 0.0f), (float)(KS_C - 1));
        float f0 = p0 - l0, f1 = p1 - l1;
        int i00 = (int)l0, i01 = min(i00 + 1, KS_C - 1);
        int i10 = (int)l1, i11 = min(i10 + 1, KS_C - 1);

        const float wa[2] = {1.0f - f0, f0};  const int ia[2] = {i00, i01};
        const float wb[2] = {1.0f - f1, f1};  const int ib[2] = {i10, i11};
        const unsigned pack = (unsigned)src | ((unsigned)dst << 8);

        #pragma unroll
        for (int a = 0; a < 2; a++)
            #pragma unroll
            for (int b = 0; b < 2; b++) {
                const int s = a * 2 + b;
                const int k = ia[a] + KS_C * ib[b];
                const int slot = el * 4 + s;
                kk[slot] = (unsigned char)k;
                rec[slot].sd = pack;
                rec[slot].w  = wa[a] * wb[b];
                atomicAdd(&cnt[k], 1);
            }
    }
    __syncthreads();

    if (tid == 0) {
        int a = 0;
        for (int k = 0; k < KK_C; k++) { off[k] = a; a += cnt[k]; }
        off[KK_C] = a;   // == RPG
    }
    __syncthreads();

    for (int j = tid; j < RPG; j += NT) {
        const int k = kk[j];
        const int p = atomicAdd(&cur[k], 1);
        d_records[g * RPG + off[k] + p] = rec[j];
    }
    if (tid <= KK_C) d_off[g * (KK_C + 1) + tid] = off[tid];
}

// ---------------------------------------------------------------------------
// Register-tiled GEMM fragment: acc[5][O/16] += src(75xI) @ Ws(IxO)
//   threads: tx = tid&15 -> O/16 cols each, ty = tid>>4 -> 5 rows each
// ---------------------------------------------------------------------------
template<int I, int O>
__device__ __forceinline__
void gemm_acc(const float* __restrict__ src, const float* __restrict__ Ws,
              int r0, int tx, float (&acc)[5][O / 16]) {
    constexpr int CP = O / 16;
    #pragma unroll 4
    for (int i = 0; i < I; i++) {
        float wv[CP];
        if constexpr (CP == 4) {
            float4 w4 = *reinterpret_cast<const float4*>(&Ws[i * O + tx * 4]);
            wv[0] = w4.x; wv[1] = w4.y; wv[2] = w4.z; wv[3] = w4.w;
        } else {
            float2 w2 = *reinterpret_cast<const float2*>(&Ws[i * O + tx * 2]);
            wv[0] = w2.x; wv[1] = w2.y;
        }
        #pragma unroll
        for (int rr = 0; rr < 5; rr++) {
            const float zv = src[(r0 + rr) * I + i];
            #pragma unroll
            for (int c = 0; c < CP; c++) acc[rr][c] = fmaf(zv, wv[c], acc[rr][c]);
        }
    }
}

// ---------------------------------------------------------------------------
// SplineConv layer: one CTA per graph
//   agg[d] = (1/deg) * sum_k z_k[d] @ W_k ;  out = elu(agg + h@root + bias)
// ---------------------------------------------------------------------------
template<int I, int O>
__global__ __launch_bounds__(NT)
void conv_kernel(const float* __restrict__ hin, const float* __restrict__ W,
                 const float* __restrict__ root, const float* __restrict__ bias,
                 float* __restrict__ hout) {
    extern __shared__ __align__(16) float sm[];
    float* hs  = sm;                   // 75*I
    float* zs  = hs + P_N * I;         // 75*I
    float* Ws  = zs + P_N * I;         // I*O
    int*   cnt = (int*)(Ws + I * O);   // 75   (record count per dst; deg = cnt/4)
    int*   off = cnt + P_N + 1;        // 26

    const int g = blockIdx.x, tid = threadIdx.x;
    constexpr int CP = O / 16;
    constexpr int LI = (I == 64) ? 6 : (I == 32) ? 5 : 0;

    for (int t = tid; t < P_N * I; t += NT) hs[t] = hin[g * P_N * I + t];
    if (tid < P_N) cnt[tid] = 0;
    if (tid <= KK_C) off[tid] = d_off[g * (KK_C + 1) + tid];
    __syncthreads();

    const Rec* __restrict__ recs = d_records + g * RPG;
    for (int j = tid; j < RPG; j += NT)
        atomicAdd(&cnt[(recs[j].sd >> 8) & 0x7F], 1);

    const int tx = tid & 15, ty = tid >> 4;
    const int r0 = ty * 5;                 // ty==15 -> r0==75 -> idle for GEMM
    float acc[5][CP];
    #pragma unroll
    for (int rr = 0; rr < 5; rr++)
        #pragma unroll
        for (int c = 0; c < CP; c++) acc[rr][c] = 0.0f;

    for (int k = 0; k < KK_C; k++) {
        __syncthreads();   // previous GEMM done reading zs/Ws (also orders cnt atomics at k==0)
        for (int t = tid; t < P_N * I; t += NT) zs[t] = 0.0f;
        for (int t = tid; t < I * O; t += NT)   Ws[t] = W[k * I * O + t];
        __syncthreads();

        const int b0 = off[k];
        const int nb = off[k + 1] - b0;
        for (int t = tid; t < nb * I; t += NT) {
            const int j = t >> LI, i = t & (I - 1);
            const Rec rc = recs[b0 + j];
            const int s = rc.sd & 0x7F, d = (rc.sd >> 8) & 0x7F;
            atomicAdd(&zs[d * I + i], rc.w * hs[s * I + i]);
        }
        __syncthreads();

        if (r0 < P_N) gemm_acc<I, O>(zs, Ws, r0, tx, acc);
    }
    __syncthreads();       // last GEMM done reading Ws before we overwrite it with root

    // mean-aggregation scale (root/bias are NOT scaled)
    float sc[5];
    #pragma unroll
    for (int rr = 0; rr < 5; rr++) {
        const int r = r0 + rr;
        sc[rr] = (r < P_N) ? 1.0f / fmaxf((float)(cnt[r] >> 2), 1.0f) : 0.0f;
    }
    #pragma unroll
    for (int rr = 0; rr < 5; rr++)
        #pragma unroll
        for (int c = 0; c < CP; c++) acc[rr][c] *= sc[rr];

    for (int t = tid; t < I * O; t += NT) Ws[t] = root[t];
    __syncthreads();
    if (r0 < P_N) gemm_acc<I, O>(hs, Ws, r0, tx, acc);

    if (r0 < P_N) {
        #pragma unroll
        for (int rr = 0; rr < 5; rr++) {
            const int r = r0 + rr;
            #pragma unroll
            for (int c = 0; c < CP; c++) {
                const int o = tx * CP + c;
                float v = acc[rr][c] + bias[o];
                hout[(g * P_N + r) * O + o] = elu_f(v);
            }
        }
    }
}

// ---------------------------------------------------------------------------
// Head: voxel max-pool (2x2 per graph) + fc1/ELU + fc2 + log_softmax
// ---------------------------------------------------------------------------
__global__ __launch_bounds__(NT)
void head_kernel(const float* __restrict__ h3, const float* __restrict__ pos,
                 const float* __restrict__ fc1w, const float* __restrict__ fc1b,
                 const float* __restrict__ fc2w, const float* __restrict__ fc2b,
                 float* __restrict__ out) {
    __shared__ float hs[P_N * 64];
    __shared__ int   vox[P_N];
    __shared__ float gx[256];
    __shared__ float f1[128];
    __shared__ float lg[10];

    const int g = blockIdx.x, tid = threadIdx.x;
    for (int t = tid; t < P_N * 64; t += NT) hs[t] = h3[g * P_N * 64 + t];
    if (tid < P_N) {
        const float p0 = pos[(g * P_N + tid) * 2 + 0];
        const float p1 = pos[(g * P_N + tid) * 2 + 1];
        const int v0 = min(max((int)(p0 / 14.0f), 0), 1);
        const int v1 = min(max((int)(p1 / 14.0f), 0), 1);
        vox[tid] = v0 + 2 * v1;
    }
    __syncthreads();

    {   // 256 threads = 4 voxels x 64 channels
        const int v = tid >> 6, c = tid & 63;
        float m = -3.402823466e38f;
        bool found = false;
        for (int r = 0; r < P_N; r++)
            if (vox[r] == v) { m = fmaxf(m, hs[r * 64 + c]); found = true; }
        gx[v * 64 + c] = found ? m : 0.0f;   // empty voxel -> 0 (matches isneginf fixup)
    }
    __syncthreads();

    if (tid < 128) {
        float a = fc1b[tid];
        #pragma unroll 8
        for (int i = 0; i < 256; i++) a = fmaf(gx[i], fc1w[i * 128 + tid], a);
        f1[tid] = elu_f(a);
    }
    __syncthreads();

    if (tid < 10) {
        float a = fc2b[tid];
        #pragma unroll 8
        for (int i = 0; i < 128; i++) a = fmaf(f1[i], fc2w[i * 10 + tid], a);
        lg[tid] = a;
    }
    __syncthreads();

    if (tid == 0) {
        float m = lg[0];
        for (int o = 1; o < 10; o++) m = fmaxf(m, lg[o]);
        float s = 0.0f;
        for (int o = 0; o < 10; o++) s += expf(lg[o] - m);
        const float lse = m + logf(s);
        for (int o = 0; o < 10; o++) out[g * 10 + o] = lg[o] - lse;
    }
}

// ---------------------------------------------------------------------------
// Launch
// ---------------------------------------------------------------------------
static int conv_smem_bytes(int I, int O) {
    return (2 * P_N * I + I * O) * 4 + (P_N + 1 + KK_C + 1) * 4 + 16;
}

extern "C" void kernel_launch(void* const* d_in, const int* in_sizes, int n_in,
                              void* d_out, int out_size) {
    const float* x     = (const float*)d_in[0];
    const int*   eidx  = (const int*)  d_in[1];
    const float* eattr = (const float*)d_in[2];
    const float* pos   = (const float*)d_in[4];
    const float* W1    = (const float*)d_in[5];
    const float* root1 = (const float*)d_in[6];
    const float* b1    = (const float*)d_in[7];
    const float* W2    = (const float*)d_in[8];
    const float* root2 = (const float*)d_in[9];
    const float* b2    = (const float*)d_in[10];
    const float* W3    = (const float*)d_in[11];
    const float* root3 = (const float*)d_in[12];
    const float* b3    = (const float*)d_in[13];
    const float* fc1w  = (const float*)d_in[14];
    const float* fc1b  = (const float*)d_in[15];
    const float* fc2w  = (const float*)d_in[16];
    const float* fc2b  = (const float*)d_in[17];
    float* out = (float*)d_out;

    void *h1p = nullptr, *h2p = nullptr, *h3p = nullptr;
    cudaGetSymbolAddress(&h1p, d_h1);
    cudaGetSymbolAddress(&h2p, d_h2);
    cudaGetSymbolAddress(&h3p, d_h3);

    const int s1 = conv_smem_bytes(1, 32);
    const int s2 = conv_smem_bytes(32, 64);
    const int s3 = conv_smem_bytes(64, 64);
    cudaFuncSetAttribute(conv_kernel<1, 32>,  cudaFuncAttributeMaxDynamicSharedMemorySize, s1);
    cudaFuncSetAttribute(conv_kernel<32, 64>, cudaFuncAttributeMaxDynamicSharedMemorySize, s2);
    cudaFuncSetAttribute(conv_kernel<64, 64>, cudaFuncAttributeMaxDynamicSharedMemorySize, s3);

    bucket_kernel<<<G_NUM, NT>>>(eidx, eattr);
    conv_kernel<1, 32> <<<G_NUM, NT, s1>>>(x,                 W1, root1, b1, (float*)h1p);
    conv_kernel<32, 64><<<G_NUM, NT, s2>>>((const float*)h1p, W2, root2, b2, (float*)h2p);
    conv_kernel<64, 64><<<G_NUM, NT, s3>>>((const float*)h2p, W3, root3, b3, (float*)h3p);
    head_kernel<<<G_NUM, NT>>>((const float*)h3p, pos, fc1w, fc1b, fc2w, fc2b, out);
}

// round 3
// speedup vs baseline: 1.3527x; 1.3527x over previous
#include <cuda_runtime.h>
#include <cuda_bf16.h>
#include <math.h>

// ---------------------------------------------------------------------------
// Problem constants
// ---------------------------------------------------------------------------
#define G_NUM  1024
#define P_N    75
#define DEG_E  8
#define N_N    (G_NUM * P_N)
#define E_N    (N_N * DEG_E)
#define EPG    (P_N * DEG_E)          // 600 edges/graph
#define RPG    (EPG * 4)              // 2400 records/graph
#define KS_C   5
#define KK_C   25                     // spline kernels
#define NMATS  26                     // 25 W_k + root
#define NKEY   (P_N * KK_C)           // 1875 (dst,k) buckets
#define NOFF   (NKEY + 1)             // 1876 offsets incl sentinel
#define YP     132                    // padded Y row stride (floats)
#define NTC    320                    // conv threads (10 warps)

// ---------------------------------------------------------------------------
// Device scratch (static — no runtime allocation)
// ---------------------------------------------------------------------------
__device__ float          d_w   [G_NUM * RPG];     // basis weights, (dst,k)-sorted
__device__ unsigned char  d_src [G_NUM * RPG];     // local src per record
__device__ unsigned short d_off2[G_NUM * NOFF];    // CSR offsets over (dst*25+k)
__device__ float d_h1[N_N * 32];
__device__ float d_h2[N_N * 64];
__device__ float d_h3[N_N * 64];

__device__ __forceinline__ float elu_f(float v) { return v > 0.0f ? v : expm1f(v); }

__device__ __forceinline__ unsigned pk2(float a, float b) {
    __nv_bfloat162 t = __floats2bfloat162_rn(a, b);
    return reinterpret_cast<unsigned&>(t);
}
__device__ __forceinline__ float bhi(float v) {
    return __bfloat162float(__float2bfloat16(v));
}

__device__ __forceinline__ void mma_bf16(float c[4], const unsigned a[4],
                                         unsigned b0, unsigned b1) {
    asm volatile(
        "mma.sync.aligned.m16n8k16.row.col.f32.bf16.bf16.f32 "
        "{%0,%1,%2,%3}, {%4,%5,%6,%7}, {%8,%9}, {%0,%1,%2,%3};"
        : "+f"(c[0]), "+f"(c[1]), "+f"(c[2]), "+f"(c[3])
        : "r"(a[0]), "r"(a[1]), "r"(a[2]), "r"(a[3]), "r"(b0), "r"(b1));
}

// ---------------------------------------------------------------------------
// Bucket kernel: spline basis + counting sort of records by (dst, k)
// ---------------------------------------------------------------------------
__global__ __launch_bounds__(256)
void bucket_kernel(const int* __restrict__ edge_index, const float* __restrict__ edge_attr) {
    __shared__ unsigned short skey[RPG];
    __shared__ unsigned char  ssr [RPG];
    __shared__ float          swt [RPG];
    __shared__ int cnt[NKEY];
    __shared__ int part[240];

    const int g = blockIdx.x, tid = threadIdx.x;
    for (int t = tid; t < NKEY; t += 256) cnt[t] = 0;
    __syncthreads();

    for (int el = tid; el < EPG; el += 256) {
        const int e  = g * EPG + el;
        const float u0 = edge_attr[2 * e], u1 = edge_attr[2 * e + 1];
        const int src = edge_index[e]       - g * P_N;
        const int dst = edge_index[E_N + e] - g * P_N;
        float p0 = u0 * (KS_C - 1), p1 = u1 * (KS_C - 1);
        float l0 = fminf(fmaxf(floorf(p0), 0.0f), (float)(KS_C - 1));
        float l1 = fminf(fmaxf(floorf(p1), 0.0f), (float)(KS_C - 1));
        float f0 = p0 - l0, f1 = p1 - l1;
        int i00 = (int)l0, i01 = min(i00 + 1, KS_C - 1);
        int i10 = (int)l1, i11 = min(i10 + 1, KS_C - 1);
        const float wa[2] = {1.0f - f0, f0};  const int ia[2] = {i00, i01};
        const float wb[2] = {1.0f - f1, f1};  const int ib[2] = {i10, i11};
        #pragma unroll
        for (int a = 0; a < 2; a++)
            #pragma unroll
            for (int b = 0; b < 2; b++) {
                const int slot = el * 4 + a * 2 + b;
                const int k = ia[a] + KS_C * ib[b];
                const int key = dst * KK_C + k;
                skey[slot] = (unsigned short)key;
                ssr [slot] = (unsigned char)src;
                swt [slot] = wa[a] * wb[b];
                atomicAdd(&cnt[key], 1);
            }
    }
    __syncthreads();

    // two-level exclusive scan over 1875 buckets
    if (tid < 235) {
        int s = 0;
        #pragma unroll
        for (int j = 0; j < 8; j++) { int idx = tid * 8 + j; if (idx < NKEY) s += cnt[idx]; }
        part[tid] = s;
    }
    __syncthreads();
    if (tid == 0) {
        int run = 0;
        for (int j = 0; j < 235; j++) { int t = part[j]; part[j] = run; run += t; }
    }
    __syncthreads();
    if (tid < 235) {
        int base = part[tid];
        #pragma unroll
        for (int j = 0; j < 8; j++) {
            int idx = tid * 8 + j;
            if (idx < NKEY) { int c = cnt[idx]; cnt[idx] = base; base += c; }
        }
    }
    __syncthreads();

    // publish offsets (before cnt is consumed as cursor)
    for (int t = tid; t < NKEY; t += 256)
        d_off2[g * NOFF + t] = (unsigned short)cnt[t];
    if (tid == 0) d_off2[g * NOFF + NKEY] = (unsigned short)RPG;
    __syncthreads();

    for (int slot = tid; slot < RPG; slot += 256) {
        const int key = skey[slot];
        const int p = atomicAdd(&cnt[key], 1);
        d_src[g * RPG + p] = ssr[slot];
        d_w  [g * RPG + p] = swt[slot];
    }
}

// ---------------------------------------------------------------------------
// Conv1 (I=1, O=32): scalar, cheap
// ---------------------------------------------------------------------------
__global__ __launch_bounds__(256)
void conv1_kernel(const float* __restrict__ x, const float* __restrict__ W1,
                  const float* __restrict__ root1, const float* __restrict__ b1,
                  float* __restrict__ out) {
    __shared__ float xs[P_N];
    __shared__ float sdk[NKEY];
    __shared__ float W1s[KK_C * 32];
    __shared__ float r1s[32], b1s[32];
    __shared__ unsigned short off2[NOFF];

    const int g = blockIdx.x, tid = threadIdx.x;
    if (tid < P_N) xs[tid] = x[g * P_N + tid];
    for (int t = tid; t < KK_C * 32; t += 256) W1s[t] = W1[t];
    if (tid < 32) { r1s[tid] = root1[tid]; b1s[tid] = b1[tid]; }
    {
        const unsigned* srcO = (const unsigned*)(d_off2 + g * NOFF);
        unsigned* dstO = (unsigned*)off2;
        for (int t = tid; t < NOFF / 2; t += 256) dstO[t] = srcO[t];
    }
    __syncthreads();

    const float* wg = d_w + g * RPG;
    const unsigned char* sg = d_src + g * RPG;
    for (int it = tid; it < NKEY; it += 256) {
        int lo = off2[it], hi = off2[it + 1];
        float s = 0.0f;
        for (int r = lo; r < hi; r++) s += wg[r] * xs[sg[r]];
        sdk[it] = s;
    }
    __syncthreads();

    for (int it = tid; it < P_N * 32; it += 256) {
        const int d = it >> 5, o = it & 31;
        float acc = 0.0f;
        #pragma unroll
        for (int k = 0; k < KK_C; k++) acc += sdk[d * KK_C + k] * W1s[k * 32 + o];
        const int rc = (int)off2[(d + 1) * KK_C] - (int)off2[d * KK_C];
        const float inv = 1.0f / (float)max(rc >> 2, 1);
        out[(g * P_N + d) * 32 + o] = elu_f(acc * inv + xs[d] * r1s[o] + b1s[o]);
    }
}

// ---------------------------------------------------------------------------
// Conv (I in {32,64}, O=64): Y = h @ [W_k | root] on bf16x3 tensor cores,
// then (dst,k)-sorted record gather. One CTA/graph, 10 warps.
// ---------------------------------------------------------------------------
template<int I>
__global__ __launch_bounds__(NTC, 2)
void convT_kernel(const float* __restrict__ hin, const float* __restrict__ W,
                  const float* __restrict__ root, const float* __restrict__ bias,
                  float* __restrict__ hout) {
    constexpr int KH  = I / 2;       // bf16 pairs along K
    constexpr int HP  = KH + 1;      // padded row stride (u32)
    constexpr int KST = I / 16;      // mma k-steps
    constexpr int WP  = KH + 1;      // padded Ws per-o stride (u32)

    extern __shared__ char smraw[];
    unsigned*       hsHi = (unsigned*)smraw;
    unsigned*       hsLo = hsHi + 80 * HP;
    unsigned*       wsHi = hsLo + 80 * HP;
    unsigned*       wsLo = wsHi + 2 * 64 * WP;
    float*          Ys   = (float*)(wsLo + 2 * 64 * WP);
    float*          sw   = Ys + 80 * YP;
    unsigned char*  ssrc = (unsigned char*)(sw + RPG);
    unsigned short* off2 = (unsigned short*)(ssrc + RPG);

    const int g = blockIdx.x, tid = threadIdx.x;

    // ---- prologue: h split to bf16 hi/lo pairs, records, offsets, W chunk 0
    for (int t = tid; t < P_N * KH; t += NTC) {
        const int r = t / KH, p = t - r * KH;
        float2 v = *(const float2*)(hin + (g * P_N + r) * I + 2 * p);
        float h0 = bhi(v.x), h1 = bhi(v.y);
        hsHi[r * HP + p] = pk2(h0, h1);
        hsLo[r * HP + p] = pk2(v.x - h0, v.y - h1);
    }
    for (int t = tid; t < 5 * KH; t += NTC) {
        const int r = 75 + t / KH, p = t % KH;
        hsHi[r * HP + p] = 0; hsLo[r * HP + p] = 0;
    }
    for (int t = tid; t < RPG; t += NTC) sw[t] = d_w[g * RPG + t];
    {
        const unsigned* s4 = (const unsigned*)(d_src + g * RPG);
        unsigned* d4 = (unsigned*)ssrc;
        for (int t = tid; t < RPG / 4; t += NTC) d4[t] = s4[t];
        const unsigned* o4 = (const unsigned*)(d_off2 + g * NOFF);
        unsigned* t4 = (unsigned*)off2;
        for (int t = tid; t < NOFF / 2; t += NTC) t4[t] = o4[t];
    }
    // stage W chunk 0 (mats 0,1): transposed [mat][o][ipair], split hi/lo
    for (int t = tid; t < 2 * 64 * KH; t += NTC) {
        const int mm = t / (64 * KH), rem = t - mm * 64 * KH;
        const int o = rem & 63, ipair = rem >> 6;
        const float* Wp = W + mm * I * 64;      // mats 0,1 always < 25
        float w0 = Wp[(2 * ipair) * 64 + o], w1 = Wp[(2 * ipair + 1) * 64 + o];
        float h0 = bhi(w0), h1 = bhi(w1);
        wsHi[(mm * 64 + o) * WP + ipair] = pk2(h0, h1);
        wsLo[(mm * 64 + o) * WP + ipair] = pk2(w0 - h0, w1 - h1);
    }
    __syncthreads();

    // ---- per-thread GEMM/gather identity
    const int w = tid >> 5, lane = tid & 31;
    const int gr = lane >> 2, cg = lane & 3;
    const int mt = w >> 1;             // 5 M-tiles, 2 warps each
    const int ntb = (w & 1) * 8;       // warp's 8 n8-jobs
    const int it = tid, d = it >> 2, q = it & 3;
    const bool hasit = (it < P_N * 4);

    // A fragments: fixed for whole kernel
    unsigned aHi[KST][4], aLo[KST][4];
    {
        const int r0 = mt * 16 + gr;
        #pragma unroll
        for (int ks = 0; ks < KST; ks++) {
            const int p0 = ks * 8 + cg;
            aHi[ks][0] = hsHi[r0 * HP + p0];       aHi[ks][1] = hsHi[(r0 + 8) * HP + p0];
            aHi[ks][2] = hsHi[r0 * HP + p0 + 4];   aHi[ks][3] = hsHi[(r0 + 8) * HP + p0 + 4];
            aLo[ks][0] = hsLo[r0 * HP + p0];       aLo[ks][1] = hsLo[(r0 + 8) * HP + p0];
            aLo[ks][2] = hsLo[r0 * HP + p0 + 4];   aLo[ks][3] = hsLo[(r0 + 8) * HP + p0 + 4];
        }
    }

    float agg[16];
    #pragma unroll
    for (int j = 0; j < 16; j++) agg[j] = 0.0f;

    for (int c = 0; c < 13; c++) {
        // ---- GEMM chunk c: Y[80, 128] = h @ [W_{2c} | W_{2c+1}]
        #pragma unroll
        for (int j = 0; j < 8; j++) {
            const int nt = ntb + j;
            const int mat = nt >> 3, n0 = (nt & 7) * 8;
            const unsigned* bh = wsHi + (mat * 64 + n0 + gr) * WP;
            const unsigned* bl = wsLo + (mat * 64 + n0 + gr) * WP;
            float Ca[4] = {0, 0, 0, 0}, Cb[4] = {0, 0, 0, 0};
            #pragma unroll
            for (int ks = 0; ks < KST; ks++) {
                const unsigned b0h = bh[ks * 8 + cg], b1h = bh[ks * 8 + cg + 4];
                const unsigned b0l = bl[ks * 8 + cg], b1l = bl[ks * 8 + cg + 4];
                mma_bf16(Ca, aHi[ks], b0h, b1h);
                mma_bf16(Cb, aLo[ks], b0h, b1h);
                mma_bf16(Cb, aHi[ks], b0l, b1l);
            }
            float* yp = Ys + (mt * 16 + gr) * YP + mat * 64 + n0 + 2 * cg;
            *(float2*)yp            = make_float2(Ca[0] + Cb[0], Ca[1] + Cb[1]);
            *(float2*)(yp + 8 * YP) = make_float2(Ca[2] + Cb[2], Ca[3] + Cb[3]);
        }
        __syncthreads();   // Y ready; Ws free

        // ---- gather chunk c into agg
        if (hasit) {
            #pragma unroll
            for (int mm = 0; mm < 2; mm++) {
                const int gm = 2 * c + mm;
                if (gm < KK_C) {
                    const int lo = off2[d * KK_C + gm], hi = off2[d * KK_C + gm + 1];
                    const float* yb = Ys + mm * 64 + q * 16;
                    for (int r = lo; r < hi; r++) {
                        const float wv = sw[r];
                        const float4* yp = (const float4*)(yb + (int)ssrc[r] * YP);
                        #pragma unroll
                        for (int jj = 0; jj < 4; jj++) {
                            float4 v = yp[jj];
                            agg[4 * jj + 0] = fmaf(wv, v.x, agg[4 * jj + 0]);
                            agg[4 * jj + 1] = fmaf(wv, v.y, agg[4 * jj + 1]);
                            agg[4 * jj + 2] = fmaf(wv, v.z, agg[4 * jj + 2]);
                            agg[4 * jj + 3] = fmaf(wv, v.w, agg[4 * jj + 3]);
                        }
                    }
                }
            }
        }
        // ---- stage next W chunk (concurrent with gather)
        if (c < 12) {
            for (int t = tid; t < 2 * 64 * KH; t += NTC) {
                const int mm = t / (64 * KH), rem = t - mm * 64 * KH;
                const int o = rem & 63, ipair = rem >> 6;
                const int gm = 2 * (c + 1) + mm;
                const float* Wp = (gm < KK_C) ? (W + gm * I * 64) : root;
                float w0 = Wp[(2 * ipair) * 64 + o], w1 = Wp[(2 * ipair + 1) * 64 + o];
                float h0 = bhi(w0), h1 = bhi(w1);
                wsHi[(mm * 64 + o) * WP + ipair] = pk2(h0, h1);
                wsLo[(mm * 64 + o) * WP + ipair] = pk2(w0 - h0, w1 - h1);
            }
        }
        __syncthreads();   // Ws(c+1) ready; gather done -> Y reusable
    }

    // ---- epilogue: mean-scale + root (chunk 12, mat slot 1) + bias + ELU
    if (hasit) {
        const int rc = (int)off2[(d + 1) * KK_C] - (int)off2[d * KK_C];
        const float inv = 1.0f / (float)max(rc >> 2, 1);
        const float* rt = Ys + d * YP + 64 + q * 16;
        float* op = hout + (g * P_N + d) * 64 + q * 16;
        #pragma unroll
        for (int jj = 0; jj < 4; jj++) {
            float4 o4;
            o4.x = elu_f(agg[4 * jj + 0] * inv + rt[4 * jj + 0] + bias[q * 16 + 4 * jj + 0]);
            o4.y = elu_f(agg[4 * jj + 1] * inv + rt[4 * jj + 1] + bias[q * 16 + 4 * jj + 1]);
            o4.z = elu_f(agg[4 * jj + 2] * inv + rt[4 * jj + 2] + bias[q * 16 + 4 * jj + 2]);
            o4.w = elu_f(agg[4 * jj + 3] * inv + rt[4 * jj + 3] + bias[q * 16 + 4 * jj + 3]);
            *(float4*)(op + 4 * jj) = o4;
        }
    }
}

// ---------------------------------------------------------------------------
// Head: voxel max-pool + fc1/ELU + fc2 + log_softmax
// ---------------------------------------------------------------------------
__global__ __launch_bounds__(256)
void head_kernel(const float* __restrict__ h3, const float* __restrict__ pos,
                 const float* __restrict__ fc1w, const float* __restrict__ fc1b,
                 const float* __restrict__ fc2w, const float* __restrict__ fc2b,
                 float* __restrict__ out) {
    __shared__ float hs[P_N * 64];
    __shared__ int   vox[P_N];
    __shared__ float gx[256];
    __shared__ float f1[128];
    __shared__ float lg[10];

    const int g = blockIdx.x, tid = threadIdx.x;
    for (int t = tid; t < P_N * 64; t += 256) hs[t] = h3[g * P_N * 64 + t];
    if (tid < P_N) {
        const float p0 = pos[(g * P_N + tid) * 2 + 0];
        const float p1 = pos[(g * P_N + tid) * 2 + 1];
        const int v0 = min(max((int)(p0 / 14.0f), 0), 1);
        const int v1 = min(max((int)(p1 / 14.0f), 0), 1);
        vox[tid] = v0 + 2 * v1;
    }
    __syncthreads();
    {
        const int v = tid >> 6, c = tid & 63;
        float m = -3.402823466e38f; bool found = false;
        for (int r = 0; r < P_N; r++)
            if (vox[r] == v) { m = fmaxf(m, hs[r * 64 + c]); found = true; }
        gx[v * 64 + c] = found ? m : 0.0f;
    }
    __syncthreads();
    if (tid < 128) {
        float a = fc1b[tid];
        #pragma unroll 8
        for (int i = 0; i < 256; i++) a = fmaf(gx[i], fc1w[i * 128 + tid], a);
        f1[tid] = elu_f(a);
    }
    __syncthreads();
    if (tid < 10) {
        float a = fc2b[tid];
        #pragma unroll 8
        for (int i = 0; i < 128; i++) a = fmaf(f1[i], fc2w[i * 10 + tid], a);
        lg[tid] = a;
    }
    __syncthreads();
    if (tid == 0) {
        float m = lg[0];
        for (int o = 1; o < 10; o++) m = fmaxf(m, lg[o]);
        float s = 0.0f;
        for (int o = 0; o < 10; o++) s += expf(lg[o] - m);
        const float lse = m + logf(s);
        for (int o = 0; o < 10; o++) out[g * 10 + o] = lg[o] - lse;
    }
}

// ---------------------------------------------------------------------------
// Launch
// ---------------------------------------------------------------------------
static int conv_smem_bytes(int I) {
    const int KH = I / 2, HP = KH + 1, WP = KH + 1;
    return (2 * 80 * HP + 2 * 2 * 64 * WP + 80 * YP + RPG) * 4 + RPG + NOFF * 2;
}

extern "C" void kernel_launch(void* const* d_in, const int* in_sizes, int n_in,
                              void* d_out, int out_size) {
    const float* x     = (const float*)d_in[0];
    const int*   eidx  = (const int*)  d_in[1];
    const float* eattr = (const float*)d_in[2];
    const float* pos   = (const float*)d_in[4];
    const float* W1    = (const float*)d_in[5];
    const float* root1 = (const float*)d_in[6];
    const float* b1    = (const float*)d_in[7];
    const float* W2    = (const float*)d_in[8];
    const float* root2 = (const float*)d_in[9];
    const float* b2    = (const float*)d_in[10];
    const float* W3    = (const float*)d_in[11];
    const float* root3 = (const float*)d_in[12];
    const float* b3    = (const float*)d_in[13];
    const float* fc1w  = (const float*)d_in[14];
    const float* fc1b  = (const float*)d_in[15];
    const float* fc2w  = (const float*)d_in[16];
    const float* fc2b  = (const float*)d_in[17];
    float* out = (float*)d_out;

    void *h1p = nullptr, *h2p = nullptr, *h3p = nullptr;
    cudaGetSymbolAddress(&h1p, d_h1);
    cudaGetSymbolAddress(&h2p, d_h2);
    cudaGetSymbolAddress(&h3p, d_h3);

    const int s2 = conv_smem_bytes(32);
    const int s3 = conv_smem_bytes(64);
    cudaFuncSetAttribute(convT_kernel<32>, cudaFuncAttributeMaxDynamicSharedMemorySize, s2);
    cudaFuncSetAttribute(convT_kernel<64>, cudaFuncAttributeMaxDynamicSharedMemorySize, s3);

    bucket_kernel<<<G_NUM, 256>>>(eidx, eattr);
    conv1_kernel<<<G_NUM, 256>>>(x, W1, root1, b1, (float*)h1p);
    convT_kernel<32><<<G_NUM, NTC, s2>>>((const float*)h1p, W2, root2, b2, (float*)h2p);
    convT_kernel<64><<<G_NUM, NTC, s3>>>((const float*)h2p, W3, root3, b3, (float*)h3p);
    head_kernel<<<G_NUM, 256>>>((const float*)h3p, pos, fc1w, fc1b, fc2w, fc2b, out);
}